// round 16
// baseline (speedup 1.0000x reference)
#include <cuda_runtime.h>
#include <cstdint>

// GraphNN R16 (= audited R14/R15): mma.sync tf32 (tcgen05 rejected by the
// harness's compute_103 PTX target). R7 cp.async pipeline + ldmatrix.x4
// fragment feed with n-major W so both A and B load non-transposed.

#define BATCH   16384
#define WIDTH   128
#define MT      64
#define KC      64
#define THREADS 256
#define NEDGE   66
#define AS_STRIDE 68              // 272B rows: LDSM conflict-free (17 odd)
#define NS_STRIDE 68
#define STAGE_FLOATS (MT * AS_STRIDE + WIDTH * NS_STRIDE)   // 4352+8704=13056
#define SMEM_BYTES (2 * STAGE_FLOATS * 4)                   // 104448

__device__ float g_scratch[10 * (size_t)BATCH * WIDTH];  // nodes 2..11 (tf32)
__device__ float g_xc[(size_t)BATCH * WIDTH];            // x tf32
__device__ float g_Wt[NEDGE * (size_t)WIDTH * WIDTH];    // W^T: [e][n][k] tf32

__device__ __forceinline__ float to_tf32(float x) {
    float r; asm("cvt.rna.tf32.f32 %0, %1;" : "=f"(r) : "f"(x)); return r;
}
__device__ __forceinline__ void cp_async16(float* smem_ptr, const float* gmem_ptr) {
    uint32_t s = (uint32_t)__cvta_generic_to_shared(smem_ptr);
    asm volatile("cp.async.cg.shared.global [%0], [%1], 16;" :: "r"(s), "l"(gmem_ptr));
}
__device__ __forceinline__ void ldsm4(uint32_t& r0, uint32_t& r1, uint32_t& r2,
                                      uint32_t& r3, uint32_t addr) {
    asm volatile("ldmatrix.sync.aligned.m8n8.x4.shared.b16 {%0,%1,%2,%3}, [%4];"
                 : "=r"(r0), "=r"(r1), "=r"(r2), "=r"(r3) : "r"(addr));
}
__device__ __forceinline__ void mma_tf32(float c[4], const uint32_t a[4],
                                         const uint32_t b[2]) {
    asm volatile(
        "mma.sync.aligned.m16n8k8.row.col.f32.tf32.tf32.f32 "
        "{%0,%1,%2,%3}, {%4,%5,%6,%7}, {%8,%9}, {%0,%1,%2,%3};"
        : "+f"(c[0]), "+f"(c[1]), "+f"(c[2]), "+f"(c[3])
        : "r"(a[0]), "r"(a[1]), "r"(a[2]), "r"(a[3]), "r"(b[0]), "r"(b[1]));
}

// one-time: tf32-round x; tf32-round + transpose W -> [e][n][k]
__global__ void convert_pre(const float* __restrict__ x, const float* __restrict__ W) {
    const size_t nx = (size_t)BATCH * WIDTH;
    const size_t nw = NEDGE * (size_t)WIDTH * WIDTH;
    for (size_t i = (size_t)blockIdx.x * blockDim.x + threadIdx.x; i < nx + nw;
         i += (size_t)gridDim.x * blockDim.x) {
        if (i < nx) { g_xc[i] = to_tf32(x[i]); }
        else {
            size_t j = i - nx;
            size_t e = j >> 14, r = j & 16383;   // r = n*128 + k
            size_t n = r >> 7, k = r & 127;
            g_Wt[j] = to_tf32(W[(e << 14) + k * WIDTH + n]);
        }
    }
}

__global__ void __launch_bounds__(THREADS, 2)
graphnn_step(const float* __restrict__ bias, float* __restrict__ dout, int v)
{
    extern __shared__ float smem[];
    const int tid  = threadIdx.x;
    const int lane = tid & 31;
    const int warp = tid >> 5;
    const int g    = lane >> 2;       // 0..7
    const int t    = lane & 3;        // 0..3
    const int wm   = warp >> 2;       // 0..1: rows wm*32
    const int wn   = warp & 3;        // 0..3: n cols wn*32
    const int m0   = blockIdx.x * MT;

    const int p      = v - 1;
    const int start  = (v - 2) * (v - 1) / 2;
    const int nchunk = 2 * p;

    // LDSM per-thread address components
    // A tiles: [(rb,k0),(rb+8,k0),(rb,k0+4),(rb+8,k0+4)] -> a0..a3
    const int a_row   = (lane & 7) + ((lane >> 3) & 1) * 8;   // + rb
    const int a_kx    = ((lane >> 4) & 1) * 4;
    // B tiles: [(nb,k0),(nb,k0+4),(nb+8,k0),(nb+8,k0+4)] -> b0/b1 of nf pairs
    const int b_row   = (lane & 7) + ((lane >> 4) & 1) * 8;   // + nb
    const int b_kx    = ((lane >> 3) & 1) * 4;

    const uint32_t smem_base = (uint32_t)__cvta_generic_to_shared(smem);

    float fin[2][4][4];
    #pragma unroll
    for (int mf = 0; mf < 2; ++mf)
        #pragma unroll
        for (int nf = 0; nf < 4; ++nf)
            #pragma unroll
            for (int j = 0; j < 4; ++j) fin[mf][nf][j] = 0.f;

    float acc[2][4][4];

    // chunk c: edge u=c>>1, k-range (c&1)*64; buffer c&1
    auto issue = [&](int c) {
        const int u  = c >> 1;
        const int kc = (c & 1) << 6;
        float* As = smem + (c & 1) * STAGE_FLOATS;
        float* Bs = As + MT * AS_STRIDE;
        const float* A = (u == 0) ? g_xc : g_scratch + (size_t)(u - 1) * BATCH * WIDTH;
        const float* B = g_Wt + (size_t)(start + u) * WIDTH * WIDTH;
        #pragma unroll
        for (int i = 0; i < 4; ++i) {            // A: 64 rows x 64 k
            int f = tid + i * THREADS;
            int r = f >> 4, c4 = (f & 15) << 2;
            cp_async16(As + r * AS_STRIDE + c4, A + (size_t)(m0 + r) * WIDTH + kc + c4);
        }
        #pragma unroll
        for (int i = 0; i < 8; ++i) {            // B: 128 n-rows x 64 k
            int f = tid + i * THREADS;
            int r = f >> 4, c4 = (f & 15) << 2;
            cp_async16(Bs + r * NS_STRIDE + c4, B + (size_t)r * WIDTH + kc + c4);
        }
        asm volatile("cp.async.commit_group;");
    };

    issue(0);

    for (int idx = 0; idx < nchunk; ++idx) {
        const int buf = idx & 1;
        if ((idx & 1) == 0) {
            #pragma unroll
            for (int mf = 0; mf < 2; ++mf)
                #pragma unroll
                for (int nf = 0; nf < 4; ++nf)
                    #pragma unroll
                    for (int j = 0; j < 4; ++j) acc[mf][nf][j] = 0.f;
        }
        if (idx + 1 < nchunk) {
            issue(idx + 1);
            asm volatile("cp.async.wait_group 1;");
        } else {
            asm volatile("cp.async.wait_group 0;");
        }
        __syncthreads();

        const uint32_t As = smem_base + (uint32_t)(buf * STAGE_FLOATS) * 4u;
        const uint32_t Bs = As + MT * AS_STRIDE * 4u;

        #pragma unroll
        for (int kk = 0; kk < KC / 8; ++kk) {
            const int k = kk * 8;
            uint32_t afr[2][4];
            #pragma unroll
            for (int mf = 0; mf < 2; ++mf) {
                const int rb = wm * 32 + mf * 16;
                ldsm4(afr[mf][0], afr[mf][1], afr[mf][2], afr[mf][3],
                      As + (uint32_t)((rb + a_row) * AS_STRIDE + k + a_kx) * 4u);
            }
            uint32_t bfr[4][2];
            #pragma unroll
            for (int np = 0; np < 2; ++np) {
                const int nb = wn * 32 + np * 16;
                ldsm4(bfr[np*2][0], bfr[np*2][1], bfr[np*2+1][0], bfr[np*2+1][1],
                      Bs + (uint32_t)((nb + b_row) * NS_STRIDE + k + b_kx) * 4u);
            }
            #pragma unroll
            for (int mf = 0; mf < 2; ++mf)
                #pragma unroll
                for (int nf = 0; nf < 4; ++nf)
                    mma_tf32(acc[mf][nf], afr[mf], bfr[nf]);
        }
        __syncthreads();

        if (idx & 1) {                            // edge complete
            const int u = idx >> 1;
            #pragma unroll
            for (int nf = 0; nf < 4; ++nf) {
                const int n  = wn * 32 + nf * 8 + t * 2;
                const float b0 = bias[(size_t)(start + u) * WIDTH + n];
                const float b1 = bias[(size_t)(start + u) * WIDTH + n + 1];
                #pragma unroll
                for (int mf = 0; mf < 2; ++mf) {
                    fin[mf][nf][0] += fmaxf(acc[mf][nf][0] + b0, 0.f);
                    fin[mf][nf][1] += fmaxf(acc[mf][nf][1] + b1, 0.f);
                    fin[mf][nf][2] += fmaxf(acc[mf][nf][2] + b0, 0.f);
                    fin[mf][nf][3] += fmaxf(acc[mf][nf][3] + b1, 0.f);
                }
            }
        }
    }

    // store node output; scratch tf32-rounded (consumed as tf32 next step)
    const bool last = (v == 12);
    float* O = last ? dout : g_scratch + (size_t)(v - 2) * BATCH * WIDTH;
    #pragma unroll
    for (int mf = 0; mf < 2; ++mf) {
        #pragma unroll
        for (int nf = 0; nf < 4; ++nf) {
            const int row = m0 + wm * 32 + mf * 16 + g;
            const int col = wn * 32 + nf * 8 + t * 2;
            float v00 = fin[mf][nf][0], v01 = fin[mf][nf][1];
            float v10 = fin[mf][nf][2], v11 = fin[mf][nf][3];
            if (!last) {
                v00 = to_tf32(v00); v01 = to_tf32(v01);
                v10 = to_tf32(v10); v11 = to_tf32(v11);
            }
            *(float2*)&O[(size_t)row * WIDTH + col]       = make_float2(v00, v01);
            *(float2*)&O[(size_t)(row + 8) * WIDTH + col] = make_float2(v10, v11);
        }
    }
}

extern "C" void kernel_launch(void* const* d_in, const int* in_sizes, int n_in,
                              void* d_out, int out_size) {
    const float* x = (const float*)d_in[0];   // (16384, 128)
    const float* W = (const float*)d_in[1];   // (66, 128, 128)
    const float* b = (const float*)d_in[2];   // (66, 128)
    float* out = (float*)d_out;               // (16384, 128)

    static bool attr_set = false;
    if (!attr_set) {
        cudaFuncSetAttribute(graphnn_step,
                             cudaFuncAttributeMaxDynamicSharedMemorySize, SMEM_BYTES);
        attr_set = true;
    }

    convert_pre<<<1024, 256>>>(x, W);
    for (int v = 2; v <= 12; ++v) {
        graphnn_step<<<BATCH / MT, THREADS, SMEM_BYTES>>>(b, out, v);
    }
}